// round 8
// baseline (speedup 1.0000x reference)
#include <cuda_runtime.h>
#include <cuda_fp16.h>

#define NN 50000
#define FF 16
#define EE 800000
#define HH 64
#define TOUT 10
#define NF (NN*FF)
#define NBIN 1024

// edge kernel geometry: warp per node, 8 warps/block
#define ETHR 256
#define EBLK (NN/8)            // 6250
// node kernel geometry: 16 warps/block, 4 nodes per warp
#define NTHRN 512
#define NPB 64                 // nodes per block
#define NBLKN ((NN + NPB - 1)/NPB)  // 782

// ---------------- device state ----------------
__device__ float   g_x0[NF];
__device__ float   g_xi[NF];
__device__ float   g_k[6][NF];
__device__ __half2 g_uv[2][NN*32];   // packed u: (.x=ch lane, .y=ch lane+32), double-buffered
__device__ float   g_v[NN*HH];
__device__ float   g_agg[NN*FF];
__device__ float   g_augproj[NN*HH];
__device__ float   g_ys[TOUT*NF];
__device__ int     g_deg[NN];
__device__ int     g_rowptr[NN+1];
__device__ int     g_wptr[NN];
__device__ int     g_src_sorted[EE];
__device__ float4  g_ea_sorted[EE];
__device__ int     g_dbin[NBIN];
__device__ int     g_dwptr[NBIN];
__device__ int     g_nodes_sorted[NN];

// DOPRI5 coefficients. Row 0 unused, rows 1..5 = A[0..4], row 6 = B.
__constant__ float c_coef[7][6] = {
  {0.f,0.f,0.f,0.f,0.f,0.f},
  {(float)(0.2), 0.f,0.f,0.f,0.f,0.f},
  {(float)(3.0/40.0), (float)(9.0/40.0), 0.f,0.f,0.f,0.f},
  {(float)(44.0/45.0), (float)(-56.0/15.0), (float)(32.0/9.0), 0.f,0.f,0.f},
  {(float)(19372.0/6561.0), (float)(-25360.0/2187.0), (float)(64448.0/6561.0), (float)(-212.0/729.0), 0.f,0.f},
  {(float)(9017.0/3168.0), (float)(-355.0/33.0), (float)(46732.0/5247.0), (float)(49.0/176.0), (float)(-5103.0/18656.0), 0.f},
  {(float)(35.0/384.0), 0.f, (float)(500.0/1113.0), (float)(125.0/192.0), (float)(-2187.0/6784.0), (float)(11.0/84.0)}
};
__constant__ float c_C[6] = {0.f, 0.2f, 0.3f, 0.8f, (float)(8.0/9.0), 1.f};

__device__ __forceinline__ float tanha(float x) {
  float r;
  asm("tanh.approx.f32 %0, %1;" : "=f"(r) : "f"(x));
  return r;
}

// ---------------- setup kernels ----------------

__global__ __launch_bounds__(256) void init_kernel(
    const float* __restrict__ xh,
    const float* __restrict__ W1m, const float* __restrict__ b1m)
{
  __shared__ float sW[32 * 64];
  __shared__ float sb[64];
  __shared__ float sxi[8][16];
  int tid = threadIdx.x;
  int gid = blockIdx.x * 256 + tid;
  if (gid < NN) g_deg[gid] = 0;
  if (gid < NBIN) g_dbin[gid] = 0;
  #pragma unroll
  for (int i = tid; i < 512; i += 256) ((float4*)sW)[i] = ((const float4*)W1m)[i];
  if (tid < 16) ((float4*)sb)[tid] = ((const float4*)b1m)[tid];
  int w = tid >> 5, lane = tid & 31;
  int n = blockIdx.x * 8 + w;
  if (n < NN) {
    if (lane < 16) {
      int idx = n * 16 + lane;
      float xv = xh[9 * NF + idx];
      g_x0[idx] = xv;
      g_xi[idx] = xv;
      sxi[w][lane] = xv;
    }
  }
  __syncthreads();
  if (n >= NN) return;
  float u0 = 0.f, u1 = 0.f;
  float v0 = sb[lane], v1 = sb[32 + lane];
  #pragma unroll
  for (int i = 0; i < 16; i++) {
    float xv = sxi[w][i];
    u0 += xv * sW[i * 64 + lane];
    u1 += xv * sW[i * 64 + 32 + lane];
    v0 += xv * sW[(16 + i) * 64 + lane];
    v1 += xv * sW[(16 + i) * 64 + 32 + lane];
  }
  g_uv[0][n * 32 + lane] = __floats2half2_rn(u0, u1);
  g_v[n * 64 + lane] = v0;
  g_v[n * 64 + 32 + lane] = v1;
}

__global__ __launch_bounds__(256) void augproj_kernel(
    const float* __restrict__ xh, const float* __restrict__ xm,
    const float* __restrict__ W1n, const float* __restrict__ b1n)
{
  __shared__ float saug[4][176];
  int tid = threadIdx.x;
  int ln = tid >> 6;
  int ch = tid & 63;
  int n = blockIdx.x * 4 + ln;
  if (ch < 16) {
    int f = ch;
    float xs[10], ms[10];
    float sm = 0.f, cm = 0.f;
    #pragma unroll
    for (int tt = 0; tt < 10; tt++) {
      xs[tt] = xh[(tt * NN + n) * FF + f];
      ms[tt] = xm[tt * NN + n];
      sm += xs[tt] * ms[tt];
      cm += ms[tt];
    }
    float cnt = fmaxf(cm, 1.0f);
    float mean = sm / cnt;
    float var = 0.f;
    #pragma unroll
    for (int tt = 0; tt < 10; tt++) { float d = xs[tt] - mean; var += d * d * ms[tt]; }
    var /= cnt;
    #pragma unroll
    for (int tt = 0; tt < 9; tt++)
      saug[ln][tt * 16 + f] = (xs[tt + 1] - xs[tt]) * (ms[tt + 1] * ms[tt]);
    saug[ln][144 + f] = mean;
    saug[ln][160 + f] = var;
  }
  __syncthreads();
  float acc = b1n[ch];
  #pragma unroll 8
  for (int r = 0; r < 176; r++)
    acc += saug[ln][r] * W1n[(32 + r) * 64 + ch];
  g_augproj[n * 64 + ch] = acc;
}

__global__ __launch_bounds__(256) void hist_kernel(const int* __restrict__ ei) {
  int e = blockIdx.x * 256 + threadIdx.x;
  if (e < EE) atomicAdd(&g_deg[ei[EE + e]], 1);
}

__global__ __launch_bounds__(1024) void scan_kernel() {
  __shared__ int wsum[32];
  int tid = threadIdx.x, lane = tid & 31, wid = tid >> 5;
  int carry = 0;
  for (int base = 0; base < NN; base += 1024) {
    int i = base + tid;
    int v = (i < NN) ? g_deg[i] : 0;
    int x = v;
    #pragma unroll
    for (int o = 1; o < 32; o <<= 1) { int y = __shfl_up_sync(0xffffffffu, x, o); if (lane >= o) x += y; }
    if (lane == 31) wsum[wid] = x;
    __syncthreads();
    if (wid == 0) {
      int s = wsum[lane];
      #pragma unroll
      for (int o = 1; o < 32; o <<= 1) { int y = __shfl_up_sync(0xffffffffu, s, o); if (lane >= o) s += y; }
      wsum[lane] = s;
    }
    __syncthreads();
    int incl = x + carry + (wid > 0 ? wsum[wid - 1] : 0);
    if (i < NN) { g_rowptr[i + 1] = incl; g_wptr[i] = incl - v; }
    carry += wsum[31];
    __syncthreads();
  }
  if (tid == 0) g_rowptr[0] = 0;
  __syncthreads();
  for (int n = tid; n < NN; n += 1024) {
    int d = g_deg[n]; if (d > NBIN - 1) d = NBIN - 1;
    atomicAdd(&g_dbin[(NBIN - 1) - d], 1);
  }
  __syncthreads();
  {
    int v = __ldcg(&g_dbin[tid]);
    int x = v;
    #pragma unroll
    for (int o = 1; o < 32; o <<= 1) { int y = __shfl_up_sync(0xffffffffu, x, o); if (lane >= o) x += y; }
    if (lane == 31) wsum[wid] = x;
    __syncthreads();
    if (wid == 0) {
      int s = wsum[lane];
      #pragma unroll
      for (int o = 1; o < 32; o <<= 1) { int y = __shfl_up_sync(0xffffffffu, s, o); if (lane >= o) s += y; }
      wsum[lane] = s;
    }
    __syncthreads();
    int incl = x + (wid > 0 ? wsum[wid - 1] : 0);
    g_dwptr[tid] = incl - v;
  }
}

__global__ __launch_bounds__(256) void scatter_kernel(
    const int* __restrict__ ei, const float* __restrict__ ea)
{
  int e = blockIdx.x * 256 + threadIdx.x;
  if (e < EE) {
    int d = ei[EE + e];
    int pos = atomicAdd(&g_wptr[d], 1);
    g_src_sorted[pos] = ei[e];
    g_ea_sorted[pos] = ((const float4*)ea)[e];
  }
  if (e < NN) {
    int dd = g_deg[e]; if (dd > NBIN - 1) dd = NBIN - 1;
    int pos = atomicAdd(&g_dwptr[(NBIN - 1) - dd], 1);
    g_nodes_sorted[pos] = e;
  }
}

// ---------------- per-stage kernel 1: lean edge gather/accumulate ----------------
// warp per node (degree-sorted), batch-of-4 load pipeline, writes agg16.
__global__ __launch_bounds__(ETHR) void edge_kernel(
    int pb,
    const float* __restrict__ W1m, const float* __restrict__ W2m,
    const float* __restrict__ b2m)
{
  __shared__ float sWea[4 * 64];
  __shared__ float sW2m[64 * 16];
  __shared__ float sb2m[16];
  __shared__ float sbuf[8][64];

  int tid = threadIdx.x;
  ((float4*)sW2m)[tid] = ((const float4*)W2m)[tid];       // 256 float4
  if (tid < 64) ((float4*)sWea)[tid] = ((const float4*)(W1m + 32 * 64))[tid];
  if (tid < 4)  ((float4*)sb2m)[tid] = ((const float4*)b2m)[tid];

  int w = tid >> 5, lane = tid & 31;
  int n = g_nodes_sorted[blockIdx.x * 8 + w];
  __syncthreads();

  const unsigned* __restrict__ U = (const unsigned*)&g_uv[pb][0];
  float v0 = g_v[n * 64 + lane];
  float v1 = g_v[n * 64 + 32 + lane];
  float wx0 = sWea[lane],        wx1 = sWea[32 + lane];
  float wy0 = sWea[64 + lane],   wy1 = sWea[96 + lane];
  float wz0 = sWea[128 + lane],  wz1 = sWea[160 + lane];
  float ww0 = sWea[192 + lane],  ww1 = sWea[224 + lane];

  float acc0 = 0.f, acc1 = 0.f;
  int beg = g_rowptr[n], end = g_rowptr[n + 1];

  int e = beg;
  // batches of 4: 4 independent u-gathers in flight
  for (; e + 4 <= end; e += 4) {
    int s0 = __ldg(g_src_sorted + e);
    int s1 = __ldg(g_src_sorted + e + 1);
    int s2 = __ldg(g_src_sorted + e + 2);
    int s3 = __ldg(g_src_sorted + e + 3);
    float4 a0 = __ldg(g_ea_sorted + e);
    float4 a1 = __ldg(g_ea_sorted + e + 1);
    float4 a2 = __ldg(g_ea_sorted + e + 2);
    float4 a3 = __ldg(g_ea_sorted + e + 3);
    unsigned u0 = __ldg(U + s0 * 32 + lane);
    unsigned u1 = __ldg(U + s1 * 32 + lane);
    unsigned u2 = __ldg(U + s2 * 32 + lane);
    unsigned u3 = __ldg(U + s3 * 32 + lane);
    {
      float2 uf = __half22float2(*reinterpret_cast<__half2*>(&u0));
      float t0 = uf.x + v0 + a0.x * wx0 + a0.y * wy0 + a0.z * wz0 + a0.w * ww0;
      float t1 = uf.y + v1 + a0.x * wx1 + a0.y * wy1 + a0.z * wz1 + a0.w * ww1;
      acc0 += tanha(t0); acc1 += tanha(t1);
    }
    {
      float2 uf = __half22float2(*reinterpret_cast<__half2*>(&u1));
      float t0 = uf.x + v0 + a1.x * wx0 + a1.y * wy0 + a1.z * wz0 + a1.w * ww0;
      float t1 = uf.y + v1 + a1.x * wx1 + a1.y * wy1 + a1.z * wz1 + a1.w * ww1;
      acc0 += tanha(t0); acc1 += tanha(t1);
    }
    {
      float2 uf = __half22float2(*reinterpret_cast<__half2*>(&u2));
      float t0 = uf.x + v0 + a2.x * wx0 + a2.y * wy0 + a2.z * wz0 + a2.w * ww0;
      float t1 = uf.y + v1 + a2.x * wx1 + a2.y * wy1 + a2.z * wz1 + a2.w * ww1;
      acc0 += tanha(t0); acc1 += tanha(t1);
    }
    {
      float2 uf = __half22float2(*reinterpret_cast<__half2*>(&u3));
      float t0 = uf.x + v0 + a3.x * wx0 + a3.y * wy0 + a3.z * wz0 + a3.w * ww0;
      float t1 = uf.y + v1 + a3.x * wx1 + a3.y * wy1 + a3.z * wz1 + a3.w * ww1;
      acc0 += tanha(t0); acc1 += tanha(t1);
    }
  }
  for (; e < end; e++) {
    int s0 = __ldg(g_src_sorted + e);
    float4 a0 = __ldg(g_ea_sorted + e);
    unsigned u0 = __ldg(U + s0 * 32 + lane);
    float2 uf = __half22float2(*reinterpret_cast<__half2*>(&u0));
    float t0 = uf.x + v0 + a0.x * wx0 + a0.y * wy0 + a0.z * wz0 + a0.w * ww0;
    float t1 = uf.y + v1 + a0.x * wx1 + a0.y * wy1 + a0.z * wz1 + a0.w * ww1;
    acc0 += tanha(t0); acc1 += tanha(t1);
  }

  // agg16 = hsum @ W2m + deg*b2m  (scalar stride-16 LDS: conflict-free)
  sbuf[w][lane] = acc0;
  sbuf[w][32 + lane] = acc1;
  __syncwarp();
  int j = lane & 15;
  int cbase = (lane < 16) ? 0 : 32;
  float p = 0.f;
  #pragma unroll
  for (int c = 0; c < 32; c++) p += sbuf[w][cbase + c] * sW2m[(cbase + c) * 16 + j];
  p += __shfl_xor_sync(0xffffffffu, p, 16);
  if (lane < 16) g_agg[n * 16 + j] = p + (float)(end - beg) * sb2m[j];
}

// ---------------- per-stage kernel 2: node MLP + RK combine + u/v projection ----------------
template<int S>
__global__ __launch_bounds__(NTHRN) void node_kernel(
    int it, int sub, int outrow, int pb,
    const float* __restrict__ t,
    const float* __restrict__ W1m, const float* __restrict__ W1n,
    const float* __restrict__ W2n, const float* __restrict__ b2n,
    const float* __restrict__ b1m)
{
  __shared__ float sW1nx[16 * 64];
  __shared__ float sW1na[16 * 64];
  __shared__ float sW2n[64 * 16];
  __shared__ float sW1m[32 * 64];
  __shared__ float swt[64];
  __shared__ float sb1m[64];
  __shared__ float sb2n[16];
  __shared__ float sbuf[16][64];
  __shared__ float sxi[16][16];
  __shared__ float sagg[16][16];
  __shared__ float sxin[16][16];

  int tid = threadIdx.x;
  for (int i = tid; i < 256; i += NTHRN) {
    ((float4*)sW1nx)[i] = ((const float4*)W1n)[i];
    ((float4*)sW1na)[i] = ((const float4*)(W1n + 1024))[i];
    ((float4*)sW2n)[i]  = ((const float4*)W2n)[i];
  }
  ((float4*)sW1m)[tid] = ((const float4*)W1m)[tid];   // 512 float4
  if (tid < 16) ((float4*)swt)[tid] = ((const float4*)(W1n + 208 * 64))[tid];
  if (tid >= 16 && tid < 32) ((float4*)sb1m)[tid - 16] = ((const float4*)b1m)[tid - 16];
  if (tid >= 32 && tid < 36) ((float4*)sb2n)[tid - 32] = ((const float4*)b2n)[tid - 32];
  __syncthreads();

  int w = tid >> 5, lane = tid & 31;
  int j = lane & 15;
  int cbase = (lane < 16) ? 0 : 32;

  float tA = __ldg(t + it), tB = __ldg(t + it + 1);
  float dti = (tB - tA) * 0.25f;
  float ti = tA + (float)sub * dti + c_C[S] * dti;
  constexpr int krow = (S < 5) ? S + 1 : 6;

  int nbase = (blockIdx.x * 16 + w) * 4;

  #pragma unroll
  for (int r = 0; r < 4; r++) {
    int n = nbase + r;
    if (n >= NN) break;   // warp-uniform

    if (lane < 16) {
      sxi[w][lane]  = g_xi[n * 16 + lane];
      sagg[w][lane] = g_agg[n * 16 + lane];
    }
    __syncwarp();

    float h0 = g_augproj[n * 64 + lane]      + ti * swt[lane];
    float h1 = g_augproj[n * 64 + 32 + lane] + ti * swt[32 + lane];
    #pragma unroll
    for (int i = 0; i < 16; i++) {
      float xv = sxi[w][i], av = sagg[w][i];
      h0 += xv * sW1nx[i * 64 + lane]      + av * sW1na[i * 64 + lane];
      h1 += xv * sW1nx[i * 64 + 32 + lane] + av * sW1na[i * 64 + 32 + lane];
    }
    __syncwarp();
    sbuf[w][lane] = tanha(h0);
    sbuf[w][32 + lane] = tanha(h1);
    __syncwarp();

    float o = 0.f;
    #pragma unroll
    for (int c = 0; c < 32; c++) o += sbuf[w][cbase + c] * sW2n[(cbase + c) * 16 + j];
    o += __shfl_xor_sync(0xffffffffu, o, 16);
    float kval = o + sb2n[j];

    if (lane < 16) {
      int idx = n * 16 + j;
      g_k[S][idx] = kval;
      float acc = c_coef[krow][S] * kval;
      #pragma unroll
      for (int jj = 0; jj < S; jj++) acc += c_coef[krow][jj] * g_k[jj][idx];
      float xv = g_x0[idx] + dti * acc;
      if (S == 5) {
        g_x0[idx] = xv;
        if (outrow >= 0) g_ys[outrow * NF + idx] = xv;
      }
      g_xi[idx] = xv;
      sxin[w][j] = xv;
    }
    __syncwarp();

    float u0 = 0.f, u1 = 0.f;
    float nv0 = sb1m[lane], nv1 = sb1m[32 + lane];
    #pragma unroll
    for (int i = 0; i < 16; i++) {
      float xv = sxin[w][i];
      u0  += xv * sW1m[i * 64 + lane];
      u1  += xv * sW1m[i * 64 + 32 + lane];
      nv0 += xv * sW1m[(16 + i) * 64 + lane];
      nv1 += xv * sW1m[(16 + i) * 64 + 32 + lane];
    }
    g_uv[pb ^ 1][n * 32 + lane] = __floats2half2_rn(u0, u1);
    g_v[n * 64 + lane] = nv0;
    g_v[n * 64 + 32 + lane] = nv1;
  }
}

__global__ __launch_bounds__(256) void gather_out_kernel(
    const int* __restrict__ mask_idx, float* __restrict__ out)
{
  int idx = blockIdx.x * 256 + threadIdx.x;
  if (idx < TOUT * NF) {
    int row = idx / NF;
    int rem = idx - row * NF;
    out[idx] = g_ys[mask_idx[row] * NF + rem];
  }
}

// ---------------- launcher ----------------
extern "C" void kernel_launch(void* const* d_in, const int* in_sizes, int n_in,
                              void* d_out, int out_size)
{
  const float* x_hist   = (const float*)d_in[0];
  const float* x_mask   = (const float*)d_in[1];
  const int*   ei       = (const int*)d_in[2];
  const float* ea       = (const float*)d_in[3];
  const float* t        = (const float*)d_in[4];
  const int*   mask_idx = (const int*)d_in[5];
  const float* W1m = (const float*)d_in[6];
  const float* b1m = (const float*)d_in[7];
  const float* W2m = (const float*)d_in[8];
  const float* b2m = (const float*)d_in[9];
  const float* W1n = (const float*)d_in[10];
  const float* b1n = (const float*)d_in[11];
  const float* W2n = (const float*)d_in[12];
  const float* b2n = (const float*)d_in[13];
  float* out = (float*)d_out;

  init_kernel<<<(NN + 7) / 8, 256>>>(x_hist, W1m, b1m);
  augproj_kernel<<<NN / 4, 256>>>(x_hist, x_mask, W1n, b1n);
  hist_kernel<<<(EE + 255) / 256, 256>>>(ei);
  scan_kernel<<<1, 1024>>>();
  scatter_kernel<<<(EE + 255) / 256, 256>>>(ei, ea);

  int L = 0;
  for (int it = 0; it < TOUT; it++) {
    for (int sub = 0; sub < 4; sub++) {
      for (int s = 0; s < 6; s++) {
        int outrow = (s == 5 && sub == 3) ? it : -1;
        int pb = L & 1;
        edge_kernel<<<EBLK, ETHR>>>(pb, W1m, W2m, b2m);
        switch (s) {
          case 0: node_kernel<0><<<NBLKN, NTHRN>>>(it, sub, outrow, pb, t, W1m, W1n, W2n, b2n, b1m); break;
          case 1: node_kernel<1><<<NBLKN, NTHRN>>>(it, sub, outrow, pb, t, W1m, W1n, W2n, b2n, b1m); break;
          case 2: node_kernel<2><<<NBLKN, NTHRN>>>(it, sub, outrow, pb, t, W1m, W1n, W2n, b2n, b1m); break;
          case 3: node_kernel<3><<<NBLKN, NTHRN>>>(it, sub, outrow, pb, t, W1m, W1n, W2n, b2n, b1m); break;
          case 4: node_kernel<4><<<NBLKN, NTHRN>>>(it, sub, outrow, pb, t, W1m, W1n, W2n, b2n, b1m); break;
          case 5: node_kernel<5><<<NBLKN, NTHRN>>>(it, sub, outrow, pb, t, W1m, W1n, W2n, b2n, b1m); break;
        }
        L++;
      }
    }
  }

  gather_out_kernel<<<(TOUT * NF + 255) / 256, 256>>>(mask_idx, out);
}